// round 7
// baseline (speedup 1.0000x reference)
#include <cuda_runtime.h>
#include <cstdint>

// Problem constants (fixed by the reference config)
#define DM 8       // d_model
#define TT 33      // seq_len
#define FFD 28     // d_ff
#define RR 3       // ffn_rank
#define NMODELS 8
#define NBATCH 4096

#define NSEQ 16                         // sequences per block (2 per thread)
#define NTHREADS (TT * NSEQ / 2)        // 264 threads, 2 tokens each
#define BLOCKS_PER_MODEL (NBATCH / NSEQ)   // 256
#define NBLOCKS (NMODELS * BLOCKS_PER_MODEL) // 2048

// KV row stride (floats) per sequence-pair: 33 tokens * 32 floats + 4 pad.
// 1060 mod 32 = 4 => spair*4 gives 8 distinct bank quads; each LDS.128
// quarter-warp phase (8 lanes, spair 0..7) covers all 32 banks exactly once.
#define KVSTRIDE (TT*32 + 4)

typedef unsigned long long u64;

// ---- TF32 rounding (matches reference's TF32 tensor-core einsums) ----
__device__ __forceinline__ float tf32r(float x) {
    uint32_t y;
    asm("cvt.rna.tf32.f32 %0, %1;" : "=r"(y) : "f"(x));
    return __uint_as_float(y);
}

// ---- packed f32x2 ops (sm_100+): one instruction, two FMAs ----
__device__ __forceinline__ u64 pk2(float lo, float hi) {
    u64 r; asm("mov.b64 %0, {%1, %2};" : "=l"(r) : "f"(lo), "f"(hi)); return r;
}
__device__ __forceinline__ void upk2(u64 v, float& lo, float& hi) {
    asm("mov.b64 {%0, %1}, %2;" : "=f"(lo), "=f"(hi) : "l"(v));
}
__device__ __forceinline__ u64 fma2(u64 a, u64 b, u64 c) {
    u64 d; asm("fma.rn.f32x2 %0, %1, %2, %3;" : "=l"(d) : "l"(a), "l"(b), "l"(c)); return d;
}
__device__ __forceinline__ u64 mul2(u64 a, u64 b) {
    u64 d; asm("mul.rn.f32x2 %0, %1, %2;" : "=l"(d) : "l"(a), "l"(b)); return d;
}

// Packed dot8 against 4 preloaded packed weight words.
__device__ __forceinline__ float dot8w(const u64* a, u64 w0, u64 w1, u64 w2, u64 w3) {
    u64 acc = mul2(a[0], w0);
    acc = fma2(a[1], w1, acc);
    acc = fma2(a[2], w2, acc);
    acc = fma2(a[3], w3, acc);
    float lo, hi; upk2(acc, lo, hi);
    return lo + hi;
}

__device__ __forceinline__ float dot8p(const u64* a, const float* w) {
    const ulonglong2* W = (const ulonglong2*)w;
    ulonglong2 w01 = W[0], w23 = W[1];
    return dot8w(a, w01.x, w01.y, w23.x, w23.y);
}

__global__ __launch_bounds__(NTHREADS, 2)
void block_fused_kernel(
    const float* __restrict__ gx,
    const float* __restrict__ gln1w, const float* __restrict__ gln1b,
    const float* __restrict__ gqkv,  const float* __restrict__ gproj,
    const float* __restrict__ gln2w, const float* __restrict__ gln2b,
    const float* __restrict__ gf1A,  const float* __restrict__ gf1B,
    const float* __restrict__ gf1W,  const float* __restrict__ gf2A,
    const float* __restrict__ gf2B,  const float* __restrict__ gf2W,
    float* __restrict__ gout)
{
    __shared__ __align__(16) float s_qkvT[3*DM][DM];   // [o][i]
    __shared__ __align__(16) float s_projT[DM][DM];    // [o][i]
    __shared__ __align__(16) float s_W1c[FFD][DM];     // [f][i] = f1Wf + f1A@f1B
    __shared__ __align__(16) float s_W2c[FFD][DM];     // [f][d] = f2Wf + f2A@f2B
    __shared__ __align__(16) float s_ln[4][DM];        // ln1w, ln1b, ln2w, ln2b
    // per (spair, token): [k_a(8) | k_b(8) | v_a(8) | v_b(8)]
    __shared__ __align__(16) float s_kv[NSEQ/2][KVSTRIDE];

    const int tid = threadIdx.x;
    const int m  = blockIdx.x / BLOCKS_PER_MODEL;
    const int b0 = (blockIdx.x % BLOCKS_PER_MODEL) * NSEQ;

    // ---- stage weights (TF32-rounded; transposed; low-rank terms folded) ----
    for (int idx = tid; idx < 3*DM*DM; idx += NTHREADS) {
        int o = idx / DM, i = idx % DM;
        s_qkvT[o][i] = tf32r(gqkv[((long)m*DM + i)*(3*DM) + o]);
    }
    for (int idx = tid; idx < DM*DM; idx += NTHREADS) {
        int o = idx / DM, i = idx % DM;
        s_projT[o][i] = tf32r(gproj[((long)m*DM + i)*DM + o]);
    }
    for (int idx = tid; idx < FFD*DM; idx += NTHREADS) {
        int f = idx / DM, i = idx % DM;
        float acc = gf1W[((long)m*DM + i)*FFD + f];
        #pragma unroll
        for (int r = 0; r < RR; r++)
            acc = fmaf(gf1A[((long)m*DM + i)*RR + r],
                       gf1B[((long)m*RR + r)*FFD + f], acc);
        s_W1c[f][i] = tf32r(acc);
    }
    for (int idx = tid; idx < FFD*DM; idx += NTHREADS) {
        int f = idx / DM, d = idx % DM;
        float acc = gf2W[((long)m*FFD + f)*DM + d];
        #pragma unroll
        for (int r = 0; r < RR; r++)
            acc = fmaf(gf2A[((long)m*FFD + f)*RR + r],
                       gf2B[((long)m*RR + r)*DM + d], acc);
        s_W2c[f][d] = tf32r(acc);
    }
    for (int idx = tid; idx < 4*DM; idx += NTHREADS) {
        int which = idx / DM, i = idx % DM;
        const float* src = (which == 0) ? gln1w : (which == 1) ? gln1b
                         : (which == 2) ? gln2w : gln2b;
        s_ln[which][i] = src[(long)m*DM + i];
    }

    __syncthreads();  // staging visible before any weight reads

    // ---- two tokens per thread: (s, t) and (s+8, t) ----
    const int sp = tid & 7;   // sequence-pair index
    const int t  = tid >> 3;  // token index (warps span 4 consecutive t)
    const long baseA = ((((long)m*NBATCH + b0 + sp    )*TT) + t) * DM;
    const long baseB = ((((long)m*NBATCH + b0 + sp + 8)*TT) + t) * DM;

    float xr[2][8];
    {
        float4 a0 = *(const float4*)(gx + baseA);
        float4 a1 = *(const float4*)(gx + baseA + 4);
        float4 c0 = *(const float4*)(gx + baseB);
        float4 c1 = *(const float4*)(gx + baseB + 4);
        xr[0][0]=a0.x; xr[0][1]=a0.y; xr[0][2]=a0.z; xr[0][3]=a0.w;
        xr[0][4]=a1.x; xr[0][5]=a1.y; xr[0][6]=a1.z; xr[0][7]=a1.w;
        xr[1][0]=c0.x; xr[1][1]=c0.y; xr[1][2]=c0.z; xr[1][3]=c0.w;
        xr[1][4]=c1.x; xr[1][5]=c1.y; xr[1][6]=c1.z; xr[1][7]=c1.w;
    }

    // LN1 (exact fp32), TF32-quantized outputs, packed
    u64 hp[2][4];
    #pragma unroll
    for (int k = 0; k < 2; k++) {
        float mean = 0.f;
        #pragma unroll
        for (int i = 0; i < 8; i++) mean += xr[k][i];
        mean *= 0.125f;
        float var = 0.f;
        #pragma unroll
        for (int i = 0; i < 8; i++) { float d = xr[k][i] - mean; var += d*d; }
        var *= 0.125f;
        float rstd = rsqrtf(var + 1e-5f);
        float h[8];
        #pragma unroll
        for (int i = 0; i < 8; i++)
            h[i] = tf32r((xr[k][i] - mean) * rstd * s_ln[0][i] + s_ln[1][i]);
        #pragma unroll
        for (int i = 0; i < 4; i++) hp[k][i] = pk2(h[2*i], h[2*i+1]);
    }

    const float qscale = 0.3535533905932738f;  // 1/sqrt(8)

    // QKV for both tokens; each weight row loaded ONCE, used twice.
    u64 qp[2][4];
    {
        float q[2][8], kvv[2][16];
        #pragma unroll
        for (int o = 0; o < 8; o++) {
            const ulonglong2* W = (const ulonglong2*)s_qkvT[o];
            ulonglong2 w01 = W[0], w23 = W[1];
            q[0][o] = tf32r(dot8w(hp[0], w01.x, w01.y, w23.x, w23.y)) * qscale;
            q[1][o] = tf32r(dot8w(hp[1], w01.x, w01.y, w23.x, w23.y)) * qscale;
        }
        #pragma unroll
        for (int o = 0; o < 16; o++) {
            const ulonglong2* W = (const ulonglong2*)s_qkvT[8 + o];
            ulonglong2 w01 = W[0], w23 = W[1];
            kvv[0][o] = tf32r(dot8w(hp[0], w01.x, w01.y, w23.x, w23.y));
            kvv[1][o] = tf32r(dot8w(hp[1], w01.x, w01.y, w23.x, w23.y));
        }
        #pragma unroll
        for (int k = 0; k < 2; k++)
            #pragma unroll
            for (int i = 0; i < 4; i++) qp[k][i] = pk2(q[k][2*i], q[k][2*i+1]);

        // layout per token: [k_a | k_b | v_a | v_b]
        float* dst = &s_kv[sp][t*32];
        #pragma unroll
        for (int i = 0; i < 2; i++) {
            ((float4*)dst)[i]     = make_float4(kvv[0][4*i], kvv[0][4*i+1], kvv[0][4*i+2], kvv[0][4*i+3]);
            ((float4*)dst)[2 + i] = make_float4(kvv[1][4*i], kvv[1][4*i+1], kvv[1][4*i+2], kvv[1][4*i+3]);
            ((float4*)dst)[4 + i] = make_float4(kvv[0][8+4*i], kvv[0][9+4*i], kvv[0][10+4*i], kvv[0][11+4*i]);
            ((float4*)dst)[6 + i] = make_float4(kvv[1][8+4*i], kvv[1][9+4*i], kvv[1][10+4*i], kvv[1][11+4*i]);
        }
    }
    __syncthreads();

    // Single-pass causal attention for both sequences (scores tiny => no max).
    u64 acc[2][4] = {{0,0,0,0},{0,0,0,0}};
    float l[2] = {0.f, 0.f};
    {
        const float* kvp = &s_kv[sp][0];
        for (int j = 0; j <= t; j++) {
            const ulonglong2* row = (const ulonglong2*)(kvp + j*32);
            ulonglong2 ka = row[0], kb = row[1];   // k_a[0..7]
            ulonglong2 kc = row[2], kd = row[3];   // k_b[0..7]
            float ea, eb;
            {
                u64 d2 = mul2(qp[0][0], ka.x);
                d2 = fma2(qp[0][1], ka.y, d2);
                d2 = fma2(qp[0][2], kb.x, d2);
                d2 = fma2(qp[0][3], kb.y, d2);
                float lo, hi; upk2(d2, lo, hi);
                ea = __expf(lo + hi);
            }
            {
                u64 d2 = mul2(qp[1][0], kc.x);
                d2 = fma2(qp[1][1], kc.y, d2);
                d2 = fma2(qp[1][2], kd.x, d2);
                d2 = fma2(qp[1][3], kd.y, d2);
                float lo, hi; upk2(d2, lo, hi);
                eb = __expf(lo + hi);
            }
            l[0] += ea;  l[1] += eb;
            u64 e2a = pk2(ea, ea), e2b = pk2(eb, eb);
            ulonglong2 va = row[4], vb = row[5];   // v_a
            ulonglong2 vc = row[6], vd = row[7];   // v_b
            acc[0][0] = fma2(e2a, va.x, acc[0][0]);
            acc[0][1] = fma2(e2a, va.y, acc[0][1]);
            acc[0][2] = fma2(e2a, vb.x, acc[0][2]);
            acc[0][3] = fma2(e2a, vb.y, acc[0][3]);
            acc[1][0] = fma2(e2b, vc.x, acc[1][0]);
            acc[1][1] = fma2(e2b, vc.y, acc[1][1]);
            acc[1][2] = fma2(e2b, vd.x, acc[1][2]);
            acc[1][3] = fma2(e2b, vd.y, acc[1][3]);
        }
    }
    u64 yp[2][4];
    #pragma unroll
    for (int k = 0; k < 2; k++) {
        float inv_l = 1.f / l[k];
        #pragma unroll
        for (int i = 0; i < 4; i++) {
            float lo, hi; upk2(acc[k][i], lo, hi);
            yp[k][i] = pk2(tf32r(lo * inv_l), tf32r(hi * inv_l));
        }
    }

    // proj + residual (shared weight row per o)
    float xa[2][8];
    #pragma unroll
    for (int o = 0; o < 8; o++) {
        const ulonglong2* W = (const ulonglong2*)s_projT[o];
        ulonglong2 w01 = W[0], w23 = W[1];
        xa[0][o] = xr[0][o] + dot8w(yp[0], w01.x, w01.y, w23.x, w23.y);
        xa[1][o] = xr[1][o] + dot8w(yp[1], w01.x, w01.y, w23.x, w23.y);
    }

    // LN2
    u64 h2p[2][4];
    #pragma unroll
    for (int k = 0; k < 2; k++) {
        float mean = 0.f;
        #pragma unroll
        for (int i = 0; i < 8; i++) mean += xa[k][i];
        mean *= 0.125f;
        float var = 0.f;
        #pragma unroll
        for (int i = 0; i < 8; i++) { float d = xa[k][i] - mean; var += d*d; }
        var *= 0.125f;
        float rstd = rsqrtf(var + 1e-5f);
        float h2[8];
        #pragma unroll
        for (int i = 0; i < 8; i++)
            h2[i] = tf32r((xa[k][i] - mean) * rstd * s_ln[2][i] + s_ln[3][i]);
        #pragma unroll
        for (int i = 0; i < 4; i++) h2p[k][i] = pk2(h2[2*i], h2[2*i+1]);
    }

    // MLP with combined weights, rows shared across the two tokens
    u64 o2[2][4] = {{0,0,0,0},{0,0,0,0}};
    #pragma unroll
    for (int f = 0; f < FFD; f++) {
        const ulonglong2* W1 = (const ulonglong2*)s_W1c[f];
        ulonglong2 u01 = W1[0], u23 = W1[1];
        float za = dot8w(h2p[0], u01.x, u01.y, u23.x, u23.y);
        float zb = dot8w(h2p[1], u01.x, u01.y, u23.x, u23.y);
        za = tf32r(0.5f * za * (1.f + erff(za * 0.7071067811865475f)));
        zb = tf32r(0.5f * zb * (1.f + erff(zb * 0.7071067811865475f)));
        u64 z2a = pk2(za, za), z2b = pk2(zb, zb);
        const ulonglong2* W2 = (const ulonglong2*)s_W2c[f];
        ulonglong2 w01 = W2[0], w23 = W2[1];
        o2[0][0] = fma2(z2a, w01.x, o2[0][0]);
        o2[0][1] = fma2(z2a, w01.y, o2[0][1]);
        o2[0][2] = fma2(z2a, w23.x, o2[0][2]);
        o2[0][3] = fma2(z2a, w23.y, o2[0][3]);
        o2[1][0] = fma2(z2b, w01.x, o2[1][0]);
        o2[1][1] = fma2(z2b, w01.y, o2[1][1]);
        o2[1][2] = fma2(z2b, w23.x, o2[1][2]);
        o2[1][3] = fma2(z2b, w23.y, o2[1][3]);
    }

    #pragma unroll
    for (int k = 0; k < 2; k++) {
        float o8[8];
        upk2(o2[k][0], o8[0], o8[1]); upk2(o2[k][1], o8[2], o8[3]);
        upk2(o2[k][2], o8[4], o8[5]); upk2(o2[k][3], o8[6], o8[7]);
        float outv[8];
        #pragma unroll
        for (int d = 0; d < 8; d++) outv[d] = xa[k][d] + o8[d];
        long base = k ? baseB : baseA;
        *(float4*)(gout + base)     = make_float4(outv[0], outv[1], outv[2], outv[3]);
        *(float4*)(gout + base + 4) = make_float4(outv[4], outv[5], outv[6], outv[7]);
    }
}

extern "C" void kernel_launch(void* const* d_in, const int* in_sizes, int n_in,
                              void* d_out, int out_size) {
    const float* x     = (const float*)d_in[0];
    const float* ln1w  = (const float*)d_in[1];
    const float* ln1b  = (const float*)d_in[2];
    const float* qkvw  = (const float*)d_in[3];
    const float* projw = (const float*)d_in[4];
    const float* ln2w  = (const float*)d_in[5];
    const float* ln2b  = (const float*)d_in[6];
    const float* f1A   = (const float*)d_in[7];
    const float* f1B   = (const float*)d_in[8];
    const float* f1W   = (const float*)d_in[9];
    const float* f2A   = (const float*)d_in[10];
    const float* f2B   = (const float*)d_in[11];
    const float* f2W   = (const float*)d_in[12];
    float* out = (float*)d_out;

    block_fused_kernel<<<NBLOCKS, NTHREADS>>>(
        x, ln1w, ln1b, qkvw, projw, ln2w, ln2b,
        f1A, f1B, f1W, f2A, f2B, f2W, out);
}